// round 3
// baseline (speedup 1.0000x reference)
#include <cuda_runtime.h>

#define NMAX 50000
#define EMAX 800000
#define GROW 512   // 32 h * 16 o

// Scratch (static device globals -- no runtime allocation)
__device__ __align__(16) float g_buf[(size_t)NMAX * GROW];   // ~102.4 MB
__device__ float xb_buf[NMAX * 16];
__device__ float sum_buf[NMAX * 16];
__device__ int   deg_src[NMAX];
__device__ int   deg_dst[NMAX];
__device__ int   base_src[NMAX];
__device__ int   cursor_src[NMAX];
__device__ int   sorted_edge[EMAX];
__device__ int   src_idx[EMAX];
__device__ int   dst_idx[EMAX];
__device__ int   idx_is64;

// ---------------------------------------------------------------------------
// Detect edge_index dtype: int64 buffers (values < 2^31, little-endian) have
// zero in every odd 32-bit word.
// ---------------------------------------------------------------------------
__global__ void detect_idx_kernel(const int* __restrict__ raw) {
    if (threadIdx.x == 0 && blockIdx.x == 0) {
        int all_zero = 1;
        for (int k = 1; k < 64; k += 2)
            if (raw[k] != 0) { all_zero = 0; break; }
        idx_is64 = all_zero;
    }
}

__global__ void decode_idx_kernel(const void* __restrict__ raw, int E) {
    int i = blockIdx.x * blockDim.x + threadIdx.x;
    if (i >= 2 * E) return;
    int v;
    if (idx_is64) v = (int)((const long long*)raw)[i];
    else          v = ((const int*)raw)[i];
    if (i < E) src_idx[i] = v;
    else       dst_idx[i - E] = v;
}

// ---------------------------------------------------------------------------
// Zero accumulators / counters.
// ---------------------------------------------------------------------------
__global__ void zero_kernel(int N) {
    int i = blockIdx.x * blockDim.x + threadIdx.x;
    if (i < N * 16) sum_buf[i] = 0.f;
    if (i < N) { deg_src[i] = 0; deg_dst[i] = 0; cursor_src[i] = 0; }
}

// ---------------------------------------------------------------------------
// Histogram: out-degree (for src grouping) and in-degree (for mean divisor).
// ---------------------------------------------------------------------------
__global__ void hist_kernel(int E) {
    int i = blockIdx.x * blockDim.x + threadIdx.x;
    if (i >= E) return;
    atomicAdd(&deg_src[src_idx[i]], 1);
    atomicAdd(&deg_dst[dst_idx[i]], 1);
}

// ---------------------------------------------------------------------------
// Exclusive scan over deg_src -> base_src. Single block of 1024 threads,
// sequential chunks + Hillis-Steele block scan.
// ---------------------------------------------------------------------------
__global__ void scan_kernel(int N) {
    __shared__ int s[1024];
    int t = threadIdx.x;
    int chunk = (N + 1023) / 1024;
    int lo = t * chunk;
    int hi = min(lo + chunk, N);
    int sum = 0;
    for (int n = lo; n < hi; n++) sum += deg_src[n];
    s[t] = sum;
    __syncthreads();
    for (int off = 1; off < 1024; off <<= 1) {
        int other = (t >= off) ? s[t - off] : 0;
        __syncthreads();
        s[t] += other;
        __syncthreads();
    }
    int run = s[t] - sum;   // exclusive prefix of this chunk
    for (int n = lo; n < hi; n++) { base_src[n] = run; run += deg_src[n]; }
}

// ---------------------------------------------------------------------------
// Scatter edge ids into src-grouped order.
// ---------------------------------------------------------------------------
__global__ void scatter_kernel(int E) {
    int i = blockIdx.x * blockDim.x + threadIdx.x;
    if (i >= E) return;
    int s = src_idx[i];
    int p = base_src[s] + atomicAdd(&cursor_src[s], 1);
    sorted_edge[p] = i;
}

// ---------------------------------------------------------------------------
// Per-node precompute:
//   g[n][h][o] = sum_i x[n][i] * w2[h*256 + i*16 + o]
//   xb[n][o]   = sum_i x[n][i] * b2[i*16 + o]
// One block (128 threads) per node; each thread produces a float4 of g.
// ---------------------------------------------------------------------------
__global__ void node_pre_kernel(const float* __restrict__ x,
                                const float* __restrict__ w2,
                                const float* __restrict__ b2) {
    int n = blockIdx.x;
    int t = threadIdx.x;          // 0..127
    __shared__ float xs[16];
    if (t < 16) xs[t] = x[n * 16 + t];
    __syncthreads();

    int c0 = t * 4;
    int h  = c0 >> 4;
    int o0 = c0 & 15;

    float4 acc = make_float4(0.f, 0.f, 0.f, 0.f);
#pragma unroll
    for (int i = 0; i < 16; i++) {
        float4 w = *reinterpret_cast<const float4*>(w2 + h * 256 + i * 16 + o0);
        float xi = xs[i];
        acc.x = fmaf(xi, w.x, acc.x);
        acc.y = fmaf(xi, w.y, acc.y);
        acc.z = fmaf(xi, w.z, acc.z);
        acc.w = fmaf(xi, w.w, acc.w);
    }
    *reinterpret_cast<float4*>(g_buf + (size_t)n * GROW + c0) = acc;

    if (t < 16) {
        float a = 0.f;
#pragma unroll
        for (int i = 0; i < 16; i++) a = fmaf(xs[i], b2[i * 16 + t], a);
        xb_buf[n * 16 + t] = a;
    }
}

// ---------------------------------------------------------------------------
// Main kernel: one warp per SOURCE node. g row lives in 16 registers/lane;
// loop over the node's edges: layer-1 MLP, contraction, atomic scatter to dst.
// ---------------------------------------------------------------------------
__global__ void node_edge_kernel(const float* __restrict__ ea,
                                 const float* __restrict__ w1,
                                 const float* __restrict__ b1,
                                 int N) {
    __shared__ float w1s[16 * 32];
    __shared__ float b1s[32];
    int tid = threadIdx.x;
    for (int j = tid; j < 16 * 32; j += blockDim.x) w1s[j] = w1[j];
    if (tid < 32) b1s[tid] = b1[tid];
    __syncthreads();

    int warp = tid >> 5;
    int lane = tid & 31;
    int n = blockIdx.x * (blockDim.x >> 5) + warp;
    if (n >= N) return;

    int deg = deg_src[n];
    if (deg == 0) return;
    int base = base_src[n];

    // g row into registers: g[k] = g_buf[n*512 + k*32 + lane]
    const float* grow = g_buf + (size_t)n * GROW;
    float g[16];
#pragma unroll
    for (int k = 0; k < 16; k++) g[k] = grow[k * 32 + lane];

    float xbv = (lane < 16) ? xb_buf[n * 16 + lane] : 0.f;
    int hb = lane >> 4;          // 0 or 1

    for (int p = 0; p < deg; p++) {
        int e   = sorted_edge[base + p];
        int dst = dst_idx[e];
        float eav = (lane < 16) ? ea[(size_t)e * 16 + lane] : 0.f;

        // layer 1: lane l owns hidden unit l (two chains)
        float a0 = b1s[lane], a1 = 0.f;
#pragma unroll
        for (int i = 0; i < 16; i += 2) {
            float x0 = __shfl_sync(0xffffffffu, eav, i);
            float x1 = __shfl_sync(0xffffffffu, eav, i + 1);
            a0 = fmaf(x0, w1s[i * 32 + lane], a0);
            a1 = fmaf(x1, w1s[(i + 1) * 32 + lane], a1);
        }
        float h = fmaxf(a0 + a1, 0.f);

        // contraction: partial_l = sum_k h[2k+hb] * g_row[k*32+l]
        float p0 = 0.f, p1 = 0.f;
#pragma unroll
        for (int k = 0; k < 16; k += 2) {
            float h0 = __shfl_sync(0xffffffffu, h, 2 * k + hb);
            float h1 = __shfl_sync(0xffffffffu, h, 2 * k + 2 + hb);
            p0 = fmaf(h0, g[k], p0);
            p1 = fmaf(h1, g[k + 1], p1);
        }
        float partial = p0 + p1;
        partial += __shfl_xor_sync(0xffffffffu, partial, 16);

        if (lane < 16)
            atomicAdd(&sum_buf[dst * 16 + lane], partial + xbv);
    }
}

// ---------------------------------------------------------------------------
// Finalize: out[n][o] = sum[n][o]/max(indeg,1) + x[n]@root[:,o] + bias[o]
// ---------------------------------------------------------------------------
__global__ void finalize_kernel(const float* __restrict__ x,
                                const float* __restrict__ root,
                                const float* __restrict__ bias,
                                float* __restrict__ out, int N) {
    int idx = blockIdx.x * blockDim.x + threadIdx.x;
    if (idx >= N * 16) return;
    int n = idx >> 4;
    int o = idx & 15;
    float c = (float)deg_dst[n];
    float a = sum_buf[idx] / fmaxf(c, 1.0f);
    float r = 0.f;
#pragma unroll
    for (int i = 0; i < 16; i++) r = fmaf(x[n * 16 + i], root[i * 16 + o], r);
    out[idx] = a + r + bias[o];
}

extern "C" void kernel_launch(void* const* d_in, const int* in_sizes, int n_in,
                              void* d_out, int out_size) {
    const float* x    = (const float*)d_in[0];
    const void*  ei   = d_in[1];
    const float* ea   = (const float*)d_in[2];
    const float* w1   = (const float*)d_in[3];
    const float* b1   = (const float*)d_in[4];
    const float* w2   = (const float*)d_in[5];
    const float* b2   = (const float*)d_in[6];
    const float* root = (const float*)d_in[7];
    const float* bias = (const float*)d_in[8];
    float*       out  = (float*)d_out;

    int N = in_sizes[0] / 16;
    int E = in_sizes[2] / 16;

    detect_idx_kernel<<<1, 32>>>((const int*)ei);
    decode_idx_kernel<<<(2 * E + 255) / 256, 256>>>(ei, E);
    zero_kernel<<<(N * 16 + 255) / 256, 256>>>(N);
    hist_kernel<<<(E + 255) / 256, 256>>>(E);
    scan_kernel<<<1, 1024>>>(N);
    scatter_kernel<<<(E + 255) / 256, 256>>>(E);

    node_pre_kernel<<<N, 128>>>(x, w2, b2);

    int warps_per_block = 8;
    int nblk = (N + warps_per_block - 1) / warps_per_block;
    node_edge_kernel<<<nblk, warps_per_block * 32>>>(ea, w1, b1, N);

    finalize_kernel<<<(N * 16 + 255) / 256, 256>>>(x, root, bias, out, N);
}

// round 4
// speedup vs baseline: 1.1148x; 1.1148x over previous
#include <cuda_runtime.h>

#define NMAX 50000
#define EMAX 800000
#define GROW 512   // 32 h * 16 o

// Scratch (static device globals -- no runtime allocation)
__device__ __align__(16) float g_buf[(size_t)NMAX * GROW];   // ~102.4 MB, permuted layout
__device__ float xb_buf[NMAX * 16];
__device__ float sum_buf[NMAX * 16];
__device__ int   deg_dst[NMAX];
__device__ int2  ed_pair[EMAX];      // (src, dst)
__device__ int   idx_is64;

// ---------------------------------------------------------------------------
// Detect edge_index dtype: int64 buffers (values < 2^31, little-endian) have
// zero in every odd 32-bit word.
// ---------------------------------------------------------------------------
__global__ void detect_idx_kernel(const int* __restrict__ raw) {
    if (threadIdx.x == 0 && blockIdx.x == 0) {
        int all_zero = 1;
        for (int k = 1; k < 64; k += 2)
            if (raw[k] != 0) { all_zero = 0; break; }
        idx_is64 = all_zero;
    }
}

// ---------------------------------------------------------------------------
// Decode edge_index into packed int2 (src, dst).
// ---------------------------------------------------------------------------
__global__ void decode_idx_kernel(const void* __restrict__ raw, int E) {
    int e = blockIdx.x * blockDim.x + threadIdx.x;
    if (e >= E) return;
    int s, d;
    if (idx_is64) {
        s = (int)((const long long*)raw)[e];
        d = (int)((const long long*)raw)[E + e];
    } else {
        s = ((const int*)raw)[e];
        d = ((const int*)raw)[E + e];
    }
    ed_pair[e] = make_int2(s, d);
}

// ---------------------------------------------------------------------------
// Zero accumulators / degree counters.
// ---------------------------------------------------------------------------
__global__ void zero_kernel(int N) {
    int i = blockIdx.x * blockDim.x + threadIdx.x;
    if (i < N * 16) sum_buf[i] = 0.f;
    if (i < N) deg_dst[i] = 0;
}

// ---------------------------------------------------------------------------
// In-degree histogram (mean divisor).
// ---------------------------------------------------------------------------
__global__ void hist_kernel(int E) {
    int i = blockIdx.x * blockDim.x + threadIdx.x;
    if (i >= E) return;
    atomicAdd(&deg_dst[ed_pair[i].y], 1);
}

// ---------------------------------------------------------------------------
// Per-node precompute with PERMUTED output layout.
//   g[h][o] = sum_i x[n][i] * w2[h*256 + i*16 + o]
// stored at G[n][ ((h&15)>>2)*128 + ((h>>4)*16 + o)*4 + (h&3) ]
// so that edge-kernel lane l reads its 16 values as 4 aligned float4s.
// One block (128 threads) per node; thread t computes (h=t>>2, o0=(4t)&15..+3).
// ---------------------------------------------------------------------------
__global__ void node_pre_kernel(const float* __restrict__ x,
                                const float* __restrict__ w2,
                                const float* __restrict__ b2) {
    int n = blockIdx.x;
    int t = threadIdx.x;          // 0..127
    __shared__ float xs[16];
    if (t < 16) xs[t] = x[n * 16 + t];
    __syncthreads();

    int h  = t >> 2;              // 0..31
    int o0 = (t * 4) & 15;        // 0,4,8,12

    float4 acc = make_float4(0.f, 0.f, 0.f, 0.f);
#pragma unroll
    for (int i = 0; i < 16; i++) {
        float4 w = *reinterpret_cast<const float4*>(w2 + h * 256 + i * 16 + o0);
        float xi = xs[i];
        acc.x = fmaf(xi, w.x, acc.x);
        acc.y = fmaf(xi, w.y, acc.y);
        acc.z = fmaf(xi, w.z, acc.z);
        acc.w = fmaf(xi, w.w, acc.w);
    }

    // permuted scatter: pos(h,o) = ((h&15)>>2)*128 + ((h>>4)*16 + o)*4 + (h&3)
    float* gn = g_buf + (size_t)n * GROW;
    int jbase = ((h & 15) >> 2) * 128 + (h >> 4) * 64 + (h & 3);
    gn[jbase + (o0 + 0) * 4] = acc.x;
    gn[jbase + (o0 + 1) * 4] = acc.y;
    gn[jbase + (o0 + 2) * 4] = acc.z;
    gn[jbase + (o0 + 3) * 4] = acc.w;

    if (t < 16) {
        float a = 0.f;
#pragma unroll
        for (int i = 0; i < 16; i++) a = fmaf(xs[i], b2[i * 16 + t], a);
        xb_buf[n * 16 + t] = a;
    }
}

// ---------------------------------------------------------------------------
// Edge kernel: persistent warps, one edge per warp-iteration.
//   layer 1 : lane l owns hidden unit l; ea via uniform float4 loads,
//             w1 column resident in registers -> 16 reg-only FMAs.
//   contract: lane l handles (o=l&15, hb=l>>4); G row read as 4 float4s
//             in the permuted layout; h values via 16 shfl broadcasts.
//   scatter : shfl_xor(16) combine, then 16-lane RED into sum_buf[dst].
// ---------------------------------------------------------------------------
__global__ void edge_kernel(const float* __restrict__ ea,
                            const float* __restrict__ w1,
                            const float* __restrict__ b1,
                            int E) {
    int lane = threadIdx.x & 31;
    int gwarp = (blockIdx.x * (blockDim.x >> 5)) + (threadIdx.x >> 5);
    int nwarps = gridDim.x * (blockDim.x >> 5);

    // per-lane weight column, loaded once
    float w1r[16];
#pragma unroll
    for (int i = 0; i < 16; i++) w1r[i] = w1[i * 32 + lane];
    float b1r = b1[lane];

    for (int e = gwarp; e < E; e += nwarps) {
        int2 sd = ed_pair[e];               // uniform across warp
        const float4* ea4 = reinterpret_cast<const float4*>(ea + (size_t)e * 16);
        float4 e0 = ea4[0], e1 = ea4[1], e2 = ea4[2], e3 = ea4[3];

        // layer 1: all-register FMA chain (two chains for ILP)
        float a0 = b1r, a1 = 0.f;
        a0 = fmaf(e0.x, w1r[0],  a0);  a1 = fmaf(e0.y, w1r[1],  a1);
        a0 = fmaf(e0.z, w1r[2],  a0);  a1 = fmaf(e0.w, w1r[3],  a1);
        a0 = fmaf(e1.x, w1r[4],  a0);  a1 = fmaf(e1.y, w1r[5],  a1);
        a0 = fmaf(e1.z, w1r[6],  a0);  a1 = fmaf(e1.w, w1r[7],  a1);
        a0 = fmaf(e2.x, w1r[8],  a0);  a1 = fmaf(e2.y, w1r[9],  a1);
        a0 = fmaf(e2.z, w1r[10], a0);  a1 = fmaf(e2.w, w1r[11], a1);
        a0 = fmaf(e3.x, w1r[12], a0);  a1 = fmaf(e3.y, w1r[13], a1);
        a0 = fmaf(e3.z, w1r[14], a0);  a1 = fmaf(e3.w, w1r[15], a1);
        float h = fmaxf(a0 + a1, 0.f);

        // contraction over permuted G row: lane l reads float4 j at
        // G + j*128 + l*4 holding h = (l>>4)*16 + 4j + p  for p=0..3
        const float4* G4 = reinterpret_cast<const float4*>(
            g_buf + (size_t)sd.x * GROW) + lane;
        int hb16 = lane & 16;
        float p0 = 0.f, p1 = 0.f, p2 = 0.f, p3 = 0.f;
#pragma unroll
        for (int j = 0; j < 4; j++) {
            float4 gv = G4[j * 32];
            int base = hb16 + 4 * j;
            float h0 = __shfl_sync(0xffffffffu, h, base + 0);
            float h1 = __shfl_sync(0xffffffffu, h, base + 1);
            float h2 = __shfl_sync(0xffffffffu, h, base + 2);
            float h3 = __shfl_sync(0xffffffffu, h, base + 3);
            p0 = fmaf(h0, gv.x, p0);
            p1 = fmaf(h1, gv.y, p1);
            p2 = fmaf(h2, gv.z, p2);
            p3 = fmaf(h3, gv.w, p3);
        }
        float partial = (p0 + p1) + (p2 + p3);
        partial += __shfl_xor_sync(0xffffffffu, partial, 16);

        if (lane < 16) {
            float msg = partial + xb_buf[sd.x * 16 + lane];
            atomicAdd(&sum_buf[sd.y * 16 + lane], msg);
        }
    }
}

// ---------------------------------------------------------------------------
// Finalize: out[n][o] = sum[n][o]/max(indeg,1) + x[n]@root[:,o] + bias[o]
// ---------------------------------------------------------------------------
__global__ void finalize_kernel(const float* __restrict__ x,
                                const float* __restrict__ root,
                                const float* __restrict__ bias,
                                float* __restrict__ out, int N) {
    int idx = blockIdx.x * blockDim.x + threadIdx.x;
    if (idx >= N * 16) return;
    int n = idx >> 4;
    int o = idx & 15;
    float c = (float)deg_dst[n];
    float a = sum_buf[idx] / fmaxf(c, 1.0f);
    float r = 0.f;
#pragma unroll
    for (int i = 0; i < 16; i++) r = fmaf(x[n * 16 + i], root[i * 16 + o], r);
    out[idx] = a + r + bias[o];
}

extern "C" void kernel_launch(void* const* d_in, const int* in_sizes, int n_in,
                              void* d_out, int out_size) {
    const float* x    = (const float*)d_in[0];
    const void*  ei   = d_in[1];
    const float* ea   = (const float*)d_in[2];
    const float* w1   = (const float*)d_in[3];
    const float* b1   = (const float*)d_in[4];
    const float* w2   = (const float*)d_in[5];
    const float* b2   = (const float*)d_in[6];
    const float* root = (const float*)d_in[7];
    const float* bias = (const float*)d_in[8];
    float*       out  = (float*)d_out;

    int N = in_sizes[0] / 16;
    int E = in_sizes[2] / 16;

    detect_idx_kernel<<<1, 32>>>((const int*)ei);
    decode_idx_kernel<<<(E + 255) / 256, 256>>>(ei, E);
    zero_kernel<<<(N * 16 + 255) / 256, 256>>>(N);
    hist_kernel<<<(E + 255) / 256, 256>>>(E);

    node_pre_kernel<<<N, 128>>>(x, w2, b2);

    edge_kernel<<<2048, 256>>>(ea, w1, b1, E);

    finalize_kernel<<<(N * 16 + 255) / 256, 256>>>(x, root, bias, out, N);
}

// round 5
// speedup vs baseline: 1.2858x; 1.1534x over previous
#include <cuda_runtime.h>
#include <cuda_fp16.h>

#define NMAX 50000
#define EMAX 800000
#define GROW 512   // 32 h * 16 o

// Scratch (static device globals -- no runtime allocation)
__device__ __align__(16) __half g_half[(size_t)NMAX * GROW];  // ~51.2 MB, permuted fp16
__device__ float xb_buf[NMAX * 16];
__device__ float sum_buf[NMAX * 16];
__device__ int   deg_dst[NMAX];
__device__ int2  ed_pair[EMAX];      // (src, dst)
__device__ int   idx_is64;

// ---------------------------------------------------------------------------
// Detect edge_index dtype: int64 buffers (values < 2^31, little-endian) have
// zero in every odd 32-bit word.
// ---------------------------------------------------------------------------
__global__ void detect_idx_kernel(const int* __restrict__ raw) {
    if (threadIdx.x == 0 && blockIdx.x == 0) {
        int all_zero = 1;
        for (int k = 1; k < 64; k += 2)
            if (raw[k] != 0) { all_zero = 0; break; }
        idx_is64 = all_zero;
    }
}

// ---------------------------------------------------------------------------
// Zero accumulators / degree counters (independent of everything else).
// ---------------------------------------------------------------------------
__global__ void zero_kernel(int N) {
    int i = blockIdx.x * blockDim.x + threadIdx.x;
    if (i < N * 16) sum_buf[i] = 0.f;
    if (i < N) deg_dst[i] = 0;
}

// ---------------------------------------------------------------------------
// Decode edge_index into packed int2 (src, dst) AND build in-degree histogram.
// ---------------------------------------------------------------------------
__global__ void decode_hist_kernel(const void* __restrict__ raw, int E) {
    int e = blockIdx.x * blockDim.x + threadIdx.x;
    if (e >= E) return;
    int s, d;
    if (idx_is64) {
        s = (int)((const long long*)raw)[e];
        d = (int)((const long long*)raw)[E + e];
    } else {
        s = ((const int*)raw)[e];
        d = ((const int*)raw)[E + e];
    }
    ed_pair[e] = make_int2(s, d);
    atomicAdd(&deg_dst[d], 1);
}

// ---------------------------------------------------------------------------
// Per-node precompute, fp16 output in a PERMUTED layout:
//   g[h][o] = sum_i x[n][i] * w2[h*256 + i*16 + o]     (fp32 math)
// stored at pos(h,o) = ((h&15)>>3)*256 + ((h>>4)*16 + o)*8 + (h&7)
// so edge-kernel lane l reads its 16 halves as 2 aligned uint4 (8 halves each):
//   uint4 j covers h = (l&16) + 8j + p (p=0..7), o = l&15.
// One block (128 threads) per node; thread t computes h=t>>2, o0=(4t)&15.
// ---------------------------------------------------------------------------
__global__ void node_pre_kernel(const float* __restrict__ x,
                                const float* __restrict__ w2,
                                const float* __restrict__ b2) {
    int n = blockIdx.x;
    int t = threadIdx.x;          // 0..127
    __shared__ float xs[16];
    if (t < 16) xs[t] = x[n * 16 + t];
    __syncthreads();

    int h  = t >> 2;              // 0..31
    int o0 = (t * 4) & 15;        // 0,4,8,12

    float4 acc = make_float4(0.f, 0.f, 0.f, 0.f);
#pragma unroll
    for (int i = 0; i < 16; i++) {
        float4 w = *reinterpret_cast<const float4*>(w2 + h * 256 + i * 16 + o0);
        float xi = xs[i];
        acc.x = fmaf(xi, w.x, acc.x);
        acc.y = fmaf(xi, w.y, acc.y);
        acc.z = fmaf(xi, w.z, acc.z);
        acc.w = fmaf(xi, w.w, acc.w);
    }

    __half* gn = g_half + (size_t)n * GROW;
    int jbase = ((h & 15) >> 3) * 256 + (h >> 4) * 128 + (h & 7);
    gn[jbase + (o0 + 0) * 8] = __float2half(acc.x);
    gn[jbase + (o0 + 1) * 8] = __float2half(acc.y);
    gn[jbase + (o0 + 2) * 8] = __float2half(acc.z);
    gn[jbase + (o0 + 3) * 8] = __float2half(acc.w);

    if (t < 16) {
        float a = 0.f;
#pragma unroll
        for (int i = 0; i < 16; i++) a = fmaf(xs[i], b2[i * 16 + t], a);
        xb_buf[n * 16 + t] = a;
    }
}

// ---------------------------------------------------------------------------
// One-edge body, inlined twice per iteration for memory-level parallelism.
// ---------------------------------------------------------------------------
__device__ __forceinline__ void do_edge(int e, int lane,
                                        const float* __restrict__ ea,
                                        const float* __restrict__ w1r,
                                        float b1r) {
    int2 sd = ed_pair[e];                       // uniform across warp
    const float4* ea4 = reinterpret_cast<const float4*>(ea + (size_t)e * 16);
    float4 e0 = ea4[0], e1 = ea4[1], e2 = ea4[2], e3 = ea4[3];

    // layer 1: all-register FMA (two chains)
    float a0 = b1r, a1 = 0.f;
    a0 = fmaf(e0.x, w1r[0],  a0);  a1 = fmaf(e0.y, w1r[1],  a1);
    a0 = fmaf(e0.z, w1r[2],  a0);  a1 = fmaf(e0.w, w1r[3],  a1);
    a0 = fmaf(e1.x, w1r[4],  a0);  a1 = fmaf(e1.y, w1r[5],  a1);
    a0 = fmaf(e1.z, w1r[6],  a0);  a1 = fmaf(e1.w, w1r[7],  a1);
    a0 = fmaf(e2.x, w1r[8],  a0);  a1 = fmaf(e2.y, w1r[9],  a1);
    a0 = fmaf(e2.z, w1r[10], a0);  a1 = fmaf(e2.w, w1r[11], a1);
    a0 = fmaf(e3.x, w1r[12], a0);  a1 = fmaf(e3.y, w1r[13], a1);
    a0 = fmaf(e3.z, w1r[14], a0);  a1 = fmaf(e3.w, w1r[15], a1);
    float h = fmaxf(a0 + a1, 0.f);

    // contraction: lane l covers (o = l&15, hb = l>>4); 2 x uint4 = 16 halves
    const uint4* G16 = reinterpret_cast<const uint4*>(
        g_half + (size_t)sd.x * GROW) + lane;
    int hb16 = lane & 16;
    float p0 = 0.f, p1 = 0.f, p2 = 0.f, p3 = 0.f;
#pragma unroll
    for (int j = 0; j < 2; j++) {
        uint4 gv = G16[j * 32];
        const __half2* hp = reinterpret_cast<const __half2*>(&gv);
        float2 f0 = __half22float2(hp[0]);
        float2 f1 = __half22float2(hp[1]);
        float2 f2 = __half22float2(hp[2]);
        float2 f3 = __half22float2(hp[3]);
        int base = hb16 + 8 * j;
        p0 = fmaf(__shfl_sync(0xffffffffu, h, base + 0), f0.x, p0);
        p1 = fmaf(__shfl_sync(0xffffffffu, h, base + 1), f0.y, p1);
        p2 = fmaf(__shfl_sync(0xffffffffu, h, base + 2), f1.x, p2);
        p3 = fmaf(__shfl_sync(0xffffffffu, h, base + 3), f1.y, p3);
        p0 = fmaf(__shfl_sync(0xffffffffu, h, base + 4), f2.x, p0);
        p1 = fmaf(__shfl_sync(0xffffffffu, h, base + 5), f2.y, p1);
        p2 = fmaf(__shfl_sync(0xffffffffu, h, base + 6), f3.x, p2);
        p3 = fmaf(__shfl_sync(0xffffffffu, h, base + 7), f3.y, p3);
    }
    float partial = (p0 + p1) + (p2 + p3);
    partial += __shfl_xor_sync(0xffffffffu, partial, 16);

    if (lane < 16) {
        float msg = partial + xb_buf[sd.x * 16 + lane];
        atomicAdd(&sum_buf[sd.y * 16 + lane], msg);
    }
}

// ---------------------------------------------------------------------------
// Edge kernel: persistent warps, TWO independent edges per iteration.
// ---------------------------------------------------------------------------
__global__ void edge_kernel(const float* __restrict__ ea,
                            const float* __restrict__ w1,
                            const float* __restrict__ b1,
                            int E) {
    int lane = threadIdx.x & 31;
    int gwarp = (blockIdx.x * (blockDim.x >> 5)) + (threadIdx.x >> 5);
    int nwarps = gridDim.x * (blockDim.x >> 5);

    float w1r[16];
#pragma unroll
    for (int i = 0; i < 16; i++) w1r[i] = w1[i * 32 + lane];
    float b1r = b1[lane];

    int stride = 2 * nwarps;
    for (int e = gwarp * 2; e < E; e += stride) {
        do_edge(e, lane, ea, w1r, b1r);
        if (e + 1 < E) do_edge(e + 1, lane, ea, w1r, b1r);
    }
}

// ---------------------------------------------------------------------------
// Finalize: out[n][o] = sum[n][o]/max(indeg,1) + x[n]@root[:,o] + bias[o]
// ---------------------------------------------------------------------------
__global__ void finalize_kernel(const float* __restrict__ x,
                                const float* __restrict__ root,
                                const float* __restrict__ bias,
                                float* __restrict__ out, int N) {
    int idx = blockIdx.x * blockDim.x + threadIdx.x;
    if (idx >= N * 16) return;
    int n = idx >> 4;
    int o = idx & 15;
    float c = (float)deg_dst[n];
    float a = sum_buf[idx] / fmaxf(c, 1.0f);
    float r = 0.f;
#pragma unroll
    for (int i = 0; i < 16; i++) r = fmaf(x[n * 16 + i], root[i * 16 + o], r);
    out[idx] = a + r + bias[o];
}

extern "C" void kernel_launch(void* const* d_in, const int* in_sizes, int n_in,
                              void* d_out, int out_size) {
    const float* x    = (const float*)d_in[0];
    const void*  ei   = d_in[1];
    const float* ea   = (const float*)d_in[2];
    const float* w1   = (const float*)d_in[3];
    const float* b1   = (const float*)d_in[4];
    const float* w2   = (const float*)d_in[5];
    const float* b2   = (const float*)d_in[6];
    const float* root = (const float*)d_in[7];
    const float* bias = (const float*)d_in[8];
    float*       out  = (float*)d_out;

    int N = in_sizes[0] / 16;
    int E = in_sizes[2] / 16;

    zero_kernel<<<(N * 16 + 255) / 256, 256>>>(N);
    detect_idx_kernel<<<1, 32>>>((const int*)ei);
    decode_hist_kernel<<<(E + 255) / 256, 256>>>(ei, E);

    node_pre_kernel<<<N, 128>>>(x, w2, b2);

    edge_kernel<<<2048, 256>>>(ea, w1, b1, E);

    finalize_kernel<<<(N * 16 + 255) / 256, 256>>>(x, root, bias, out, N);
}

// round 6
// speedup vs baseline: 1.5918x; 1.2380x over previous
#include <cuda_runtime.h>
#include <cuda_fp16.h>

#define NMAX 50000
#define EMAX 800000
#define GROW 512   // 32 h * 16 o
#define NODES_PER_BLOCK 64

// Scratch (static device globals -- no runtime allocation)
__device__ __align__(16) __half g_half[(size_t)NMAX * GROW];  // ~51.2 MB, permuted fp16
__device__ __align__(16) float w2p[16 * GROW];                // permuted fp32 w2
__device__ float xb_buf[NMAX * 16];
__device__ float sum_buf[NMAX * 16];
__device__ int   deg_dst[NMAX];
__device__ int2  ed_pair[EMAX];      // (src, dst)
__device__ int   idx_is64;

// ---------------------------------------------------------------------------
// Detect edge_index dtype (1 warp, ballot). int64 buffers (values < 2^31,
// little-endian) have zero in every odd 32-bit word.
// ---------------------------------------------------------------------------
__global__ void detect_idx_kernel(const int* __restrict__ raw) {
    int t = threadIdx.x;                 // 32 threads
    int v = raw[1 + 2 * t];
    unsigned m = __ballot_sync(0xffffffffu, v != 0);
    if (t == 0) idx_is64 = (m == 0u);
}

// ---------------------------------------------------------------------------
// Zero accumulators / degree counters.
// ---------------------------------------------------------------------------
__global__ void zero_kernel(int N) {
    int i = blockIdx.x * blockDim.x + threadIdx.x;
    if (i < N * 16) sum_buf[i] = 0.f;
    if (i < N) deg_dst[i] = 0;
}

// ---------------------------------------------------------------------------
// Decode edge_index into packed int2 (src, dst) AND build in-degree histogram.
// ---------------------------------------------------------------------------
__global__ void decode_hist_kernel(const void* __restrict__ raw, int E) {
    int e = blockIdx.x * blockDim.x + threadIdx.x;
    if (e >= E) return;
    int s, d;
    if (idx_is64) {
        s = (int)((const long long*)raw)[e];
        d = (int)((const long long*)raw)[E + e];
    } else {
        s = ((const int*)raw)[e];
        d = ((const int*)raw)[E + e];
    }
    ed_pair[e] = make_int2(s, d);
    atomicAdd(&deg_dst[d], 1);
}

// ---------------------------------------------------------------------------
// Permute w2 once:  w2p[i*512 + pos] = w2[h*256 + i*16 + o]
// where pos(h,o) = ((h&15)>>3)*256 + ((h>>4)*16 + o)*8 + (h&7).
// ---------------------------------------------------------------------------
__global__ void w2_perm_kernel(const float* __restrict__ w2) {
    int idx = blockIdx.x * blockDim.x + threadIdx.x;
    if (idx >= 16 * GROW) return;
    int i   = idx >> 9;
    int pos = idx & 511;
    int j  = pos >> 8;
    int q  = (pos >> 3) & 31;
    int hb = q >> 4;
    int o  = q & 15;
    int p  = pos & 7;
    int h  = hb * 16 + j * 8 + p;
    w2p[idx] = w2[h * 256 + i * 16 + o];
}

// ---------------------------------------------------------------------------
// Per-node precompute: block of 128 threads handles 64 nodes.
// w2p staged in smem (32KB). Thread t owns 4 CONTIGUOUS permuted outputs
// -> one coalesced 8B fp16 store per node. fp32 math.
// ---------------------------------------------------------------------------
__global__ void node_pre_kernel(const float* __restrict__ x,
                                const float* __restrict__ b2,
                                int N) {
    __shared__ float w2s[16 * GROW];            // 32 KB
    __shared__ float xs[NODES_PER_BLOCK * 16];  // 4 KB
    __shared__ float b2s[256];                  // 1 KB
    int t = threadIdx.x;                        // 0..127

    for (int j = t; j < 16 * GROW / 4; j += 128)
        reinterpret_cast<float4*>(w2s)[j] = reinterpret_cast<const float4*>(w2p)[j];
    for (int j = t; j < 256; j += 128) b2s[j] = b2[j];

    int nbase = blockIdx.x * NODES_PER_BLOCK;
    int ncnt  = min(NODES_PER_BLOCK, N - nbase);
    for (int j = t; j < ncnt * 16; j += 128) xs[j] = x[nbase * 16 + j];
    __syncthreads();

    for (int ln = 0; ln < ncnt; ln++) {
        int n = nbase + ln;
        const float4* xr = reinterpret_cast<const float4*>(xs + ln * 16);
        float4 xa = xr[0], xbv = xr[1], xc = xr[2], xd = xr[3];

        float4 acc = make_float4(0.f, 0.f, 0.f, 0.f);
#pragma unroll
        for (int i = 0; i < 16; i++) {
            float xi;
            switch (i >> 2) {
                case 0: xi = (i & 3) == 0 ? xa.x : (i & 3) == 1 ? xa.y : (i & 3) == 2 ? xa.z : xa.w; break;
                case 1: xi = (i & 3) == 0 ? xbv.x : (i & 3) == 1 ? xbv.y : (i & 3) == 2 ? xbv.z : xbv.w; break;
                case 2: xi = (i & 3) == 0 ? xc.x : (i & 3) == 1 ? xc.y : (i & 3) == 2 ? xc.z : xc.w; break;
                default: xi = (i & 3) == 0 ? xd.x : (i & 3) == 1 ? xd.y : (i & 3) == 2 ? xd.z : xd.w; break;
            }
            float4 w = reinterpret_cast<const float4*>(w2s + i * GROW)[t];
            acc.x = fmaf(xi, w.x, acc.x);
            acc.y = fmaf(xi, w.y, acc.y);
            acc.z = fmaf(xi, w.z, acc.z);
            acc.w = fmaf(xi, w.w, acc.w);
        }

        __half2 h0 = __floats2half2_rn(acc.x, acc.y);
        __half2 h1 = __floats2half2_rn(acc.z, acc.w);
        uint2 pk;
        pk.x = *reinterpret_cast<unsigned*>(&h0);
        pk.y = *reinterpret_cast<unsigned*>(&h1);
        *reinterpret_cast<uint2*>(g_half + (size_t)n * GROW + t * 4) = pk;

        if (t < 16) {
            const float* xrs = xs + ln * 16;
            float a = 0.f;
#pragma unroll
            for (int i = 0; i < 16; i++) a = fmaf(xrs[i], b2s[i * 16 + t], a);
            xb_buf[n * 16 + t] = a;
        }
    }
}

// ---------------------------------------------------------------------------
// One-edge body. h pairs packed into half2 -> 8 contraction shfls (was 16).
// ---------------------------------------------------------------------------
__device__ __forceinline__ void do_edge(int e, int lane,
                                        const float* __restrict__ ea,
                                        const float* __restrict__ w1r,
                                        float b1r) {
    int2 sd = ed_pair[e];                       // uniform across warp
    const float4* ea4 = reinterpret_cast<const float4*>(ea + (size_t)e * 16);
    float4 e0 = ea4[0], e1 = ea4[1], e2 = ea4[2], e3 = ea4[3];

    // layer 1: all-register FMA (two chains)
    float a0 = b1r, a1 = 0.f;
    a0 = fmaf(e0.x, w1r[0],  a0);  a1 = fmaf(e0.y, w1r[1],  a1);
    a0 = fmaf(e0.z, w1r[2],  a0);  a1 = fmaf(e0.w, w1r[3],  a1);
    a0 = fmaf(e1.x, w1r[4],  a0);  a1 = fmaf(e1.y, w1r[5],  a1);
    a0 = fmaf(e1.z, w1r[6],  a0);  a1 = fmaf(e1.w, w1r[7],  a1);
    a0 = fmaf(e2.x, w1r[8],  a0);  a1 = fmaf(e2.y, w1r[9],  a1);
    a0 = fmaf(e2.z, w1r[10], a0);  a1 = fmaf(e2.w, w1r[11], a1);
    a0 = fmaf(e3.x, w1r[12], a0);  a1 = fmaf(e3.y, w1r[13], a1);
    a0 = fmaf(e3.z, w1r[14], a0);  a1 = fmaf(e3.w, w1r[15], a1);
    float h = fmaxf(a0 + a1, 0.f);

    // pack neighbor pair: every lane ends with half2(h[2m], h[2m+1]), m=lane>>1
    float hn = __shfl_xor_sync(0xffffffffu, h, 1);
    float plo = (lane & 1) ? hn : h;
    float phi = (lane & 1) ? h : hn;
    __half2 hp2 = __floats2half2_rn(plo, phi);
    unsigned hpu = *reinterpret_cast<unsigned*>(&hp2);

    // contraction: lane l covers (o=l&15, hb=l>>4); 2 x uint4 = 16 halves
    const uint4* G16 = reinterpret_cast<const uint4*>(
        g_half + (size_t)sd.x * GROW) + lane;
    int hb16 = lane & 16;
    float p0 = 0.f, p1 = 0.f, p2 = 0.f, p3 = 0.f;
#pragma unroll
    for (int j = 0; j < 2; j++) {
        uint4 gv = G16[j * 32];
        const __half2* gp = reinterpret_cast<const __half2*>(&gv);
        int b = hb16 + 8 * j;
        unsigned q0 = __shfl_sync(0xffffffffu, hpu, b + 0);
        unsigned q1 = __shfl_sync(0xffffffffu, hpu, b + 2);
        unsigned q2 = __shfl_sync(0xffffffffu, hpu, b + 4);
        unsigned q3 = __shfl_sync(0xffffffffu, hpu, b + 6);
        float2 h0 = __half22float2(*reinterpret_cast<__half2*>(&q0));
        float2 h1 = __half22float2(*reinterpret_cast<__half2*>(&q1));
        float2 h2 = __half22float2(*reinterpret_cast<__half2*>(&q2));
        float2 h3 = __half22float2(*reinterpret_cast<__half2*>(&q3));
        float2 f0 = __half22float2(gp[0]);
        float2 f1 = __half22float2(gp[1]);
        float2 f2 = __half22float2(gp[2]);
        float2 f3 = __half22float2(gp[3]);
        p0 = fmaf(h0.x, f0.x, p0);  p1 = fmaf(h0.y, f0.y, p1);
        p2 = fmaf(h1.x, f1.x, p2);  p3 = fmaf(h1.y, f1.y, p3);
        p0 = fmaf(h2.x, f2.x, p0);  p1 = fmaf(h2.y, f2.y, p1);
        p2 = fmaf(h3.x, f3.x, p2);  p3 = fmaf(h3.y, f3.y, p3);
    }
    float partial = (p0 + p1) + (p2 + p3);
    partial += __shfl_xor_sync(0xffffffffu, partial, 16);

    if (lane < 16) {
        float msg = partial + xb_buf[sd.x * 16 + lane];
        atomicAdd(&sum_buf[sd.y * 16 + lane], msg);
    }
}

// ---------------------------------------------------------------------------
// Edge kernel: persistent warps, TWO independent edges per iteration.
// ---------------------------------------------------------------------------
__global__ void edge_kernel(const float* __restrict__ ea,
                            const float* __restrict__ w1,
                            const float* __restrict__ b1,
                            int E) {
    int lane = threadIdx.x & 31;
    int gwarp = (blockIdx.x * (blockDim.x >> 5)) + (threadIdx.x >> 5);
    int nwarps = gridDim.x * (blockDim.x >> 5);

    float w1r[16];
#pragma unroll
    for (int i = 0; i < 16; i++) w1r[i] = w1[i * 32 + lane];
    float b1r = b1[lane];

    int stride = 2 * nwarps;
    for (int e = gwarp * 2; e < E; e += stride) {
        do_edge(e, lane, ea, w1r, b1r);
        if (e + 1 < E) do_edge(e + 1, lane, ea, w1r, b1r);
    }
}

// ---------------------------------------------------------------------------
// Finalize: out[n][o] = sum[n][o]/max(indeg,1) + x[n]@root[:,o] + bias[o]
// ---------------------------------------------------------------------------
__global__ void finalize_kernel(const float* __restrict__ x,
                                const float* __restrict__ root,
                                const float* __restrict__ bias,
                                float* __restrict__ out, int N) {
    int idx = blockIdx.x * blockDim.x + threadIdx.x;
    if (idx >= N * 16) return;
    int n = idx >> 4;
    int o = idx & 15;
    float c = (float)deg_dst[n];
    float a = sum_buf[idx] / fmaxf(c, 1.0f);
    float r = 0.f;
#pragma unroll
    for (int i = 0; i < 16; i++) r = fmaf(x[n * 16 + i], root[i * 16 + o], r);
    out[idx] = a + r + bias[o];
}

extern "C" void kernel_launch(void* const* d_in, const int* in_sizes, int n_in,
                              void* d_out, int out_size) {
    const float* x    = (const float*)d_in[0];
    const void*  ei   = d_in[1];
    const float* ea   = (const float*)d_in[2];
    const float* w1   = (const float*)d_in[3];
    const float* b1   = (const float*)d_in[4];
    const float* w2   = (const float*)d_in[5];
    const float* b2   = (const float*)d_in[6];
    const float* root = (const float*)d_in[7];
    const float* bias = (const float*)d_in[8];
    float*       out  = (float*)d_out;

    int N = in_sizes[0] / 16;
    int E = in_sizes[2] / 16;

    zero_kernel<<<(N * 16 + 255) / 256, 256>>>(N);
    detect_idx_kernel<<<1, 32>>>((const int*)ei);
    w2_perm_kernel<<<(16 * GROW + 255) / 256, 256>>>(w2);
    decode_hist_kernel<<<(E + 255) / 256, 256>>>(ei, E);

    node_pre_kernel<<<(N + NODES_PER_BLOCK - 1) / NODES_PER_BLOCK, 128>>>(x, b2, N);

    edge_kernel<<<2048, 256>>>(ea, w1, b1, E);

    finalize_kernel<<<(N * 16 + 255) / 256, 256>>>(x, root, bias, out, N);
}